// round 6
// baseline (speedup 1.0000x reference)
#include <cuda_runtime.h>
#include <math.h>

// ElasticBand (NEB) — chunk-pipelined RO fusion.
// Chunks of 4 interior images. Kernel RO_c runs two INDEPENDENT streams:
//   reduce-stream: rolling 6-dot reduction over chunk c (cold DRAM reads,
//                  fills L2 for the next kernel's out-stream)
//   out-stream:    rolling output for chunk c-1 (reads are L2 hits from RO_{c-1},
//                  coefficients published by the tiny S_{c-1} kernel in between)
// No grid barriers, no spinning, no co-residency requirements.

#define KMAXC 0.1f
#define DLTKC 0.02f
#define EPSC  0.1f
#define PI_F  3.14159265358979323846f

#define TA    256                // threads per block
#define KPT   2                  // float4 per thread
#define TILEA (TA * KPT)         // 512 float4 per block
#define NW    (TA / 32)          // warps per block
#define MAX_INT 62
#define MAX_NB  1280
#define CHUNK   4                // interior images per chunk

// per-(image,block,warp) partials: [ii][block][warp][6]
__device__ float g_part[(size_t)MAX_INT * MAX_NB * NW * 6];
__device__ float g_escal[MAX_INT * 6];   // cp, cm, km, kp, mult
__device__ float g_coef[MAX_INT * 4];    // g1, alpha, beta

__device__ __forceinline__ float warpSum(float v) {
    #pragma unroll
    for (int o = 16; o > 0; o >>= 1) v += __shfl_xor_sync(0xffffffffu, v, o);
    return v;
}

__device__ __forceinline__ float spring_k(float ea, float eb, float emax, float eref) {
    float ei = fmaxf(ea, eb);
    float k = KMAXC - DLTKC * (emax - ei) / (emax - eref);
    if (ei < eref) k = KMAXC - DLTKC;
    return k;
}

// ---- eng-only precompute (1 tiny block) -------------------------------------
__global__ void nebInit(const float* __restrict__ eng, int n_img)
{
    if (threadIdx.x != 0) return;

    float emin = eng[0], emax = eng[0];
    int imax = 0;
    for (int p = 1; p < n_img; p++) {
        float e = eng[p];
        if (e < emin) emin = e;
        if (e > emax) { emax = e; imax = p; }   // strict > keeps first max
    }
    const float eref = emin - EPSC;
    const int n_int = n_img - 2;

    for (int j = 0; j < n_int; j++) {
        const int i = j + 1;
        const float e0 = eng[i - 1], e1 = eng[i], e2 = eng[i + 1];
        const float km = spring_k(e0, e1, emax, eref);
        const float kp = spring_k(e1, e2, emax, eref);

        float cp, cm;
        if (e2 > e1 && e1 > e0)      { cp = 1.f;  cm = 0.f; }
        else if (e2 < e1 && e1 < e0) { cp = 0.f;  cm = 1.f; }
        else {
            float d1 = fabsf(e2 - e1), d0 = fabsf(e0 - e1);
            float dvmax = fmaxf(d1, d0), dvmin = fminf(d1, d0);
            if (e2 > e1)      { cp = dvmax; cm = dvmin; }
            else if (e2 < e1) { cp = dvmin; cm = dvmax; }
            else              { cp = 0.f;   cm = 0.f; }
        }
        const float mult = (j == imax) ? 2.f : 1.f;  // .at[i_raw] quirk

        g_escal[j * 6 + 0] = cp;
        g_escal[j * 6 + 1] = cm;
        g_escal[j * 6 + 2] = km;
        g_escal[j * 6 + 3] = kp;
        g_escal[j * 6 + 4] = mult;
    }
}

// ---- coefficient math --------------------------------------------------------
__device__ __forceinline__ void coefFrom(
    const float* S, int ii, float& g1, float& al, float& be)
{
    const float A = S[0], B = S[1], C = S[2], D = S[3], E = S[4], W = S[5];
    const float cp = g_escal[ii * 6 + 0];
    const float cm = g_escal[ii * 6 + 1];
    const float km = g_escal[ii * 6 + 2];
    const float kp = g_escal[ii * 6 + 3];
    const float mu = g_escal[ii * 6 + 4];

    const float Stt = cp * cp * A + 2.f * cp * cm * C + cm * cm * B;
    const float Sft = cp * D + cm * E;
    const float a   = Sft / Stt;
    const float s   = (kp * sqrtf(B) - km * sqrtf(A)) / sqrtf(Stt);

    const float F   = W - Sft * Sft / Stt;
    const float Tm  = cp * C + cm * B;
    const float Tp  = cp * A + cm * C;
    const float St  = kp * Tm - km * Tp;
    const float Gv  = kp * kp * B + km * km * A - 2.f * kp * km * C
                      - 2.f * s * St + s * s * Stt;
    const float Sf  = kp * E - km * D;
    const float H   = Sf - a * St - s * Sft + s * a * Stt;

    const float sw  = (2.0f / PI_F) * atan2f(F, Gv);
    const float Hsw = H * sw;

    g1 = 1.f - Hsw;
    al = a * (Hsw - mu) * cp - km;
    be = a * (Hsw - mu) * cm + kp;
}

// ---- S: fold per-warp partials -> coefficients for one image -----------------
__global__ void nebScalarsC(int ia, int nb)
{
    const int ii = (ia - 1) + blockIdx.x;
    const int t  = threadIdx.x;          // 256
    const int total = nb * NW;

    float acc[6] = {0.f, 0.f, 0.f, 0.f, 0.f, 0.f};
    for (int p = t; p < total; p += 256) {
        const float* pp = &g_part[((size_t)ii * nb * NW + p) * 6];
        #pragma unroll
        for (int c = 0; c < 6; c++) acc[c] += pp[c];
    }

    __shared__ float sred[6][8];
    #pragma unroll
    for (int c = 0; c < 6; c++) {
        float r = warpSum(acc[c]);
        if ((t & 31) == 0) sred[c][t >> 5] = r;
    }
    __syncthreads();

    if (t == 0) {
        float S[6];
        #pragma unroll
        for (int c = 0; c < 6; c++) {
            float s = 0.f;
            #pragma unroll
            for (int w = 0; w < 8; w++) s += sred[c][w];
            S[c] = s;
        }
        float g1, al, be;
        coefFrom(S, ii, g1, al, be);
        g_coef[ii * 4 + 0] = g1;
        g_coef[ii * 4 + 1] = al;
        g_coef[ii * 4 + 2] = be;
    }
}

// ---- RO: reduce-stream over [ia,ib) + out-stream over [oa,ob) -----------------
__global__ void __launch_bounds__(TA) nebRO(
    const float4* __restrict__ pos4,
    const float4* __restrict__ frc4,
    float4* __restrict__ out4,
    int nvec, int n_img, int nb,
    int ia, int ib, int oa, int ob,
    int copyFirst, int copyLast)
{
    const int b    = blockIdx.x;
    const int t    = threadIdx.x;
    const int warp = t >> 5;
    const int lane = t & 31;

    int  idx[KPT];
    bool ok[KPT];
    #pragma unroll
    for (int k = 0; k < KPT; k++) {
        idx[k] = b * TILEA + k * TA + t;
        ok[k]  = (idx[k] < nvec);
    }

    if (copyFirst) {
        #pragma unroll
        for (int k = 0; k < KPT; k++) {
            if (ok[k]) {
                float4 f0 = __ldcs(&frc4[idx[k]]);
                __stcs(&out4[idx[k]], f0);
            }
        }
    }

    const int lenR = ib - ia;
    const int lenO = ob - oa;
    const int len  = (lenR > lenO) ? lenR : lenO;
    const float4 z = make_float4(0.f, 0.f, 0.f, 0.f);

    // reduce-stream rolling window (plain loads: cache in L2 for next out-stream)
    float4 pR[KPT], dpR[KPT];
    if (lenR > 0) {
        #pragma unroll
        for (int k = 0; k < KPT; k++) {
            pR[k] = z; dpR[k] = z;
            if (ok[k]) {
                float4 pm = pos4[(size_t)(ia - 1) * nvec + idx[k]];
                pR[k]     = pos4[(size_t)ia * nvec + idx[k]];
                dpR[k].x = pR[k].x - pm.x; dpR[k].y = pR[k].y - pm.y;
                dpR[k].z = pR[k].z - pm.z; dpR[k].w = pR[k].w - pm.w;
            }
        }
    }

    // out-stream rolling window (L2-hit reads, last-use)
    float4 pO[KPT], dpO[KPT];
    if (lenO > 0) {
        #pragma unroll
        for (int k = 0; k < KPT; k++) {
            pO[k] = z; dpO[k] = z;
            if (ok[k]) {
                float4 pm = __ldcs(&pos4[(size_t)(oa - 1) * nvec + idx[k]]);
                pO[k]     = __ldcs(&pos4[(size_t)oa * nvec + idx[k]]);
                dpO[k].x = pO[k].x - pm.x; dpO[k].y = pO[k].y - pm.y;
                dpO[k].z = pO[k].z - pm.z; dpO[k].w = pO[k].w - pm.w;
            }
        }
    }

    for (int s = 0; s < len; s++) {
        // ---- reduce one image (cold reads) ----
        if (s < lenR) {
            const int i  = ia + s;
            const int ii = i - 1;
            float vA = 0.f, vB = 0.f, vC = 0.f, vD = 0.f, vE = 0.f, vW = 0.f;

            #pragma unroll
            for (int k = 0; k < KPT; k++) {
                if (ok[k]) {
                    float4 pN = pos4[(size_t)(i + 1) * nvec + idx[k]];
                    float4 f  = frc4[(size_t)i * nvec + idx[k]];

                    float dmx = pN.x - pR[k].x, dmy = pN.y - pR[k].y;
                    float dmz = pN.z - pR[k].z, dmw = pN.w - pR[k].w;

                    vA = fmaf(dpR[k].x, dpR[k].x, fmaf(dpR[k].y, dpR[k].y, fmaf(dpR[k].z, dpR[k].z, fmaf(dpR[k].w, dpR[k].w, vA))));
                    vB = fmaf(dmx, dmx, fmaf(dmy, dmy, fmaf(dmz, dmz, fmaf(dmw, dmw, vB))));
                    vC = fmaf(dpR[k].x, dmx, fmaf(dpR[k].y, dmy, fmaf(dpR[k].z, dmz, fmaf(dpR[k].w, dmw, vC))));
                    vD = fmaf(f.x, dpR[k].x, fmaf(f.y, dpR[k].y, fmaf(f.z, dpR[k].z, fmaf(f.w, dpR[k].w, vD))));
                    vE = fmaf(f.x, dmx, fmaf(f.y, dmy, fmaf(f.z, dmz, fmaf(f.w, dmw, vE))));
                    vW = fmaf(f.x, f.x, fmaf(f.y, f.y, fmaf(f.z, f.z, fmaf(f.w, f.w, vW))));

                    dpR[k].x = dmx; dpR[k].y = dmy; dpR[k].z = dmz; dpR[k].w = dmw;
                    pR[k] = pN;
                }
            }

            float vals[6] = { vA, vB, vC, vD, vE, vW };
            #pragma unroll
            for (int c = 0; c < 6; c++) vals[c] = warpSum(vals[c]);
            if (lane == 0) {
                float* pp = &g_part[(((size_t)ii * nb + b) * NW + warp) * 6];
                #pragma unroll
                for (int c = 0; c < 6; c++) pp[c] = vals[c];
            }
        }

        // ---- output one image (L2-hot reads, stream writes) ----
        if (s < lenO) {
            const int i  = oa + s;
            const int ii = i - 1;
            const float g1 = __ldg(&g_coef[ii * 4 + 0]);
            const float al = __ldg(&g_coef[ii * 4 + 1]);
            const float be = __ldg(&g_coef[ii * 4 + 2]);

            #pragma unroll
            for (int k = 0; k < KPT; k++) {
                if (ok[k]) {
                    float4 pN = __ldcs(&pos4[(size_t)(i + 1) * nvec + idx[k]]);
                    float4 f  = __ldcs(&frc4[(size_t)i * nvec + idx[k]]);

                    float dmx = pN.x - pO[k].x, dmy = pN.y - pO[k].y;
                    float dmz = pN.z - pO[k].z, dmw = pN.w - pO[k].w;

                    float4 o;
                    o.x = fmaf(g1, f.x, fmaf(al, dpO[k].x, be * dmx));
                    o.y = fmaf(g1, f.y, fmaf(al, dpO[k].y, be * dmy));
                    o.z = fmaf(g1, f.z, fmaf(al, dpO[k].z, be * dmz));
                    o.w = fmaf(g1, f.w, fmaf(al, dpO[k].w, be * dmw));
                    __stcs(&out4[(size_t)i * nvec + idx[k]], o);

                    dpO[k].x = dmx; dpO[k].y = dmy; dpO[k].z = dmz; dpO[k].w = dmw;
                    pO[k] = pN;
                }
            }
        }
    }

    if (copyLast) {
        #pragma unroll
        for (int k = 0; k < KPT; k++) {
            if (ok[k]) {
                size_t g = (size_t)(n_img - 1) * nvec + idx[k];
                float4 fl = __ldcs(&frc4[g]);
                __stcs(&out4[g], fl);
            }
        }
    }
}

// =============================================================================
extern "C" void kernel_launch(void* const* d_in, const int* in_sizes, int n_in,
                              void* d_out, int out_size)
{
    const float* pos = (const float*)d_in[0];
    const float* frc = (const float*)d_in[1];
    const float* eng = (const float*)d_in[2];

    const int n_img    = in_sizes[2];                 // 32
    const long per_img = (long)in_sizes[0] / n_img;   // 1,200,000 floats
    const int  nvec    = (int)(per_img / 4);          // 300,000 float4
    const int  n_int   = n_img - 2;

    const float4* pos4 = (const float4*)pos;
    const float4* frc4 = (const float4*)frc;
    float4* out4 = (float4*)d_out;

    const int nb = (nvec + TILEA - 1) / TILEA;        // 586 blocks

    if (n_int < 1) {
        nebRO<<<nb, TA>>>(pos4, frc4, out4, nvec, n_img, nb,
                          1, 1, 1, 1, 1, (n_img > 1) ? 1 : 0);
        return;
    }

    nebInit<<<1, 32>>>(eng, n_img);

    // chunk boundaries over interior images [1, n_img-1)
    int starts[MAX_INT + 1];
    int nChunks = (n_int + CHUNK - 1) / CHUNK;
    int base = n_int / nChunks, rem = n_int % nChunks;
    starts[0] = 1;
    for (int c = 0; c < nChunks; c++)
        starts[c + 1] = starts[c] + base + (c < rem ? 1 : 0);

    // pipeline: RO_c reduces chunk c and outputs chunk c-1
    for (int c = 0; c <= nChunks; c++) {
        int ia = (c < nChunks) ? starts[c] : 1;       // reduce range
        int ib = (c < nChunks) ? starts[c + 1] : 1;   // (empty on last)
        int oa = (c > 0) ? starts[c - 1] : 1;         // out range
        int ob = (c > 0) ? starts[c] : 1;             // (empty on first)

        nebRO<<<nb, TA>>>(pos4, frc4, out4, nvec, n_img, nb,
                          ia, ib, oa, ob,
                          (c == 0) ? 1 : 0,
                          (c == nChunks) ? 1 : 0);

        if (c < nChunks)
            nebScalarsC<<<(ib - ia), 256>>>(ia, nb);
    }
}

// round 7
// speedup vs baseline: 1.3291x; 1.3291x over previous
#include <cuda_runtime.h>
#include <math.h>

// ElasticBand (NEB) — flat 3-pass scheme, every pass at the DRAM roofline.
// Pass R (flat 2D): one block per (interior image, atom chunk); 8 independent
//   loads per thread, single block reduce, no loops -> full MLP, ~6.2 TB/s.
//   Image index on blockIdx.x so a wave covers all images for a chunk band:
//   the 3x pos reads dedup in L2 (DRAM ~= pos once + frc once).
// Pass S: fold 586 block partials per image + eng logic -> (g1, alpha, beta).
// Pass O (flat): out = g1*frc + alpha*dp + beta*dm, pos reads L2-deduped.

#define KMAXC 0.1f
#define DLTKC 0.02f
#define EPSC  0.1f
#define PI_F  3.14159265358979323846f

#define TA    256                // threads per block
#define KPT   2                  // float4 per thread
#define TILEA (TA * KPT)         // 512 float4 per block
#define MAX_INT 62
#define MAX_NB  1280

__device__ float g_part[(size_t)MAX_INT * MAX_NB * 6];  // [ii][block][6]
__device__ float g_escal[MAX_INT * 6];                   // cp, cm, km, kp, mult
__device__ float g_coef[MAX_INT * 4];                    // g1, alpha, beta

__device__ __forceinline__ float warpSum(float v) {
    #pragma unroll
    for (int o = 16; o > 0; o >>= 1) v += __shfl_xor_sync(0xffffffffu, v, o);
    return v;
}

__device__ __forceinline__ float spring_k(float ea, float eb, float emax, float eref) {
    float ei = fmaxf(ea, eb);
    float k = KMAXC - DLTKC * (emax - ei) / (emax - eref);
    if (ei < eref) k = KMAXC - DLTKC;
    return k;
}

// ---- eng-only precompute (1 tiny block) -------------------------------------
__global__ void nebInit(const float* __restrict__ eng, int n_img)
{
    if (threadIdx.x != 0) return;

    float emin = eng[0], emax = eng[0];
    int imax = 0;
    for (int p = 1; p < n_img; p++) {
        float e = eng[p];
        if (e < emin) emin = e;
        if (e > emax) { emax = e; imax = p; }   // strict > keeps first max
    }
    const float eref = emin - EPSC;
    const int n_int = n_img - 2;

    for (int j = 0; j < n_int; j++) {
        const int i = j + 1;
        const float e0 = eng[i - 1], e1 = eng[i], e2 = eng[i + 1];
        const float km = spring_k(e0, e1, emax, eref);
        const float kp = spring_k(e1, e2, emax, eref);

        float cp, cm;
        if (e2 > e1 && e1 > e0)      { cp = 1.f;  cm = 0.f; }
        else if (e2 < e1 && e1 < e0) { cp = 0.f;  cm = 1.f; }
        else {
            float d1 = fabsf(e2 - e1), d0 = fabsf(e0 - e1);
            float dvmax = fmaxf(d1, d0), dvmin = fminf(d1, d0);
            if (e2 > e1)      { cp = dvmax; cm = dvmin; }
            else if (e2 < e1) { cp = dvmin; cm = dvmax; }
            else              { cp = 0.f;   cm = 0.f; }
        }
        const float mult = (j == imax) ? 2.f : 1.f;  // .at[i_raw] quirk

        g_escal[j * 6 + 0] = cp;
        g_escal[j * 6 + 1] = cm;
        g_escal[j * 6 + 2] = km;
        g_escal[j * 6 + 3] = kp;
        g_escal[j * 6 + 4] = mult;
    }
}

// ---- coefficient math --------------------------------------------------------
__device__ __forceinline__ void coefFrom(
    const float* S, int ii, float& g1, float& al, float& be)
{
    const float A = S[0], B = S[1], C = S[2], D = S[3], E = S[4], W = S[5];
    const float cp = g_escal[ii * 6 + 0];
    const float cm = g_escal[ii * 6 + 1];
    const float km = g_escal[ii * 6 + 2];
    const float kp = g_escal[ii * 6 + 3];
    const float mu = g_escal[ii * 6 + 4];

    const float Stt = cp * cp * A + 2.f * cp * cm * C + cm * cm * B;
    const float Sft = cp * D + cm * E;
    const float a   = Sft / Stt;
    const float s   = (kp * sqrtf(B) - km * sqrtf(A)) / sqrtf(Stt);

    const float F   = W - Sft * Sft / Stt;
    const float Tm  = cp * C + cm * B;
    const float Tp  = cp * A + cm * C;
    const float St  = kp * Tm - km * Tp;
    const float Gv  = kp * kp * B + km * km * A - 2.f * kp * km * C
                      - 2.f * s * St + s * s * Stt;
    const float Sf  = kp * E - km * D;
    const float H   = Sf - a * St - s * Sft + s * a * Stt;

    const float sw  = (2.0f / PI_F) * atan2f(F, Gv);
    const float Hsw = H * sw;

    g1 = 1.f - Hsw;
    al = a * (Hsw - mu) * cp - km;
    be = a * (Hsw - mu) * cm + kp;
}

// ---- R: flat 2D reduce. block = (image ii = blockIdx.x, chunk b = blockIdx.y) -
__global__ void __launch_bounds__(TA) nebReduceF(
    const float4* __restrict__ pos4,
    const float4* __restrict__ frc4,
    int nvec, int nb)
{
    const int ii = blockIdx.x;        // interior index
    const int i  = ii + 1;            // global image
    const int b  = blockIdx.y;        // atom chunk
    const int t  = threadIdx.x;

    float vA = 0.f, vB = 0.f, vC = 0.f, vD = 0.f, vE = 0.f, vW = 0.f;

    #pragma unroll
    for (int k = 0; k < KPT; k++) {
        const int j = b * TILEA + k * TA + t;
        if (j < nvec) {
            const size_t base = (size_t)i * nvec + j;
            float4 pm = pos4[base - nvec];
            float4 pc = pos4[base];
            float4 pp = pos4[base + nvec];
            float4 f  = frc4[base];

            float dpx = pc.x - pm.x, dmx = pp.x - pc.x;
            float dpy = pc.y - pm.y, dmy = pp.y - pc.y;
            float dpz = pc.z - pm.z, dmz = pp.z - pc.z;
            float dpw = pc.w - pm.w, dmw = pp.w - pc.w;

            vA = fmaf(dpx, dpx, fmaf(dpy, dpy, fmaf(dpz, dpz, fmaf(dpw, dpw, vA))));
            vB = fmaf(dmx, dmx, fmaf(dmy, dmy, fmaf(dmz, dmz, fmaf(dmw, dmw, vB))));
            vC = fmaf(dpx, dmx, fmaf(dpy, dmy, fmaf(dpz, dmz, fmaf(dpw, dmw, vC))));
            vD = fmaf(f.x, dpx, fmaf(f.y, dpy, fmaf(f.z, dpz, fmaf(f.w, dpw, vD))));
            vE = fmaf(f.x, dmx, fmaf(f.y, dmy, fmaf(f.z, dmz, fmaf(f.w, dmw, vE))));
            vW = fmaf(f.x, f.x, fmaf(f.y, f.y, fmaf(f.z, f.z, fmaf(f.w, f.w, vW))));
        }
    }

    __shared__ float sred[6][TA / 32];
    float vals[6] = { vA, vB, vC, vD, vE, vW };
    #pragma unroll
    for (int c = 0; c < 6; c++) {
        float r = warpSum(vals[c]);
        if ((t & 31) == 0) sred[c][t >> 5] = r;
    }
    __syncthreads();
    if (t < 6) {
        float s = 0.f;
        #pragma unroll
        for (int w = 0; w < TA / 32; w++) s += sred[t][w];
        g_part[((size_t)ii * nb + b) * 6 + t] = s;
    }
}

// ---- S: fold block partials -> coefficients ----------------------------------
__global__ void nebScalars(int nb)
{
    const int j = blockIdx.x;    // interior index
    const int t = threadIdx.x;   // 256

    float acc[6] = {0.f, 0.f, 0.f, 0.f, 0.f, 0.f};
    for (int b = t; b < nb; b += blockDim.x) {
        const float* pp = &g_part[((size_t)j * nb + b) * 6];
        #pragma unroll
        for (int c = 0; c < 6; c++) acc[c] += pp[c];
    }

    __shared__ float sred[6][8];
    #pragma unroll
    for (int c = 0; c < 6; c++) {
        float r = warpSum(acc[c]);
        if ((t & 31) == 0) sred[c][t >> 5] = r;
    }
    __syncthreads();

    if (t == 0) {
        float S[6];
        #pragma unroll
        for (int c = 0; c < 6; c++) {
            float s = 0.f;
            #pragma unroll
            for (int w = 0; w < 8; w++) s += sred[c][w];
            S[c] = s;
        }
        float g1, al, be;
        coefFrom(S, j, g1, al, be);
        g_coef[j * 4 + 0] = g1;
        g_coef[j * 4 + 1] = al;
        g_coef[j * 4 + 2] = be;
    }
}

// ---- O: flat streaming output (proven ~6.1 TB/s) ------------------------------
__global__ void nebOut(
    const float4* __restrict__ pos4,
    const float4* __restrict__ frc4,
    float4* __restrict__ out4,
    int nvec, int n_img)
{
    size_t gid = (size_t)blockIdx.x * blockDim.x + threadIdx.x;
    size_t total = (size_t)n_img * nvec;
    if (gid >= total) return;

    int img = (int)(gid / (unsigned)nvec);
    float4 f = frc4[gid];

    if (img == 0 || img == n_img - 1) { out4[gid] = f; return; }

    const int ii = img - 1;
    const float g1 = __ldg(&g_coef[ii * 4 + 0]);
    const float al = __ldg(&g_coef[ii * 4 + 1]);
    const float be = __ldg(&g_coef[ii * 4 + 2]);

    float4 pm = pos4[gid - nvec];
    float4 pc = pos4[gid];
    float4 pp = pos4[gid + nvec];

    float4 o;
    o.x = fmaf(g1, f.x, fmaf(al, pc.x - pm.x, be * (pp.x - pc.x)));
    o.y = fmaf(g1, f.y, fmaf(al, pc.y - pm.y, be * (pp.y - pc.y)));
    o.z = fmaf(g1, f.z, fmaf(al, pc.z - pm.z, be * (pp.z - pc.z)));
    o.w = fmaf(g1, f.w, fmaf(al, pc.w - pm.w, be * (pp.w - pc.w)));
    out4[gid] = o;
}

// =============================================================================
extern "C" void kernel_launch(void* const* d_in, const int* in_sizes, int n_in,
                              void* d_out, int out_size)
{
    const float* pos = (const float*)d_in[0];
    const float* frc = (const float*)d_in[1];
    const float* eng = (const float*)d_in[2];

    const int n_img    = in_sizes[2];                 // 32
    const long per_img = (long)in_sizes[0] / n_img;   // 1,200,000 floats
    const int  nvec    = (int)(per_img / 4);          // 300,000 float4
    const int  n_int   = n_img - 2;

    const float4* pos4 = (const float4*)pos;
    const float4* frc4 = (const float4*)frc;
    float4* out4 = (float4*)d_out;

    const int nb = (nvec + TILEA - 1) / TILEA;        // 586 chunks

    size_t total = (size_t)n_img * nvec;
    int blocksC = (int)((total + 255) / 256);

    if (n_int < 1) {
        nebOut<<<blocksC, 256>>>(pos4, frc4, out4, nvec, n_img);
        return;
    }

    nebInit<<<1, 32>>>(eng, n_img);
    nebReduceF<<<dim3(n_int, nb), TA>>>(pos4, frc4, nvec, nb);
    nebScalars<<<n_int, 256>>>(nb);
    nebOut<<<blocksC, 256>>>(pos4, frc4, out4, nvec, n_img);
}